// round 12
// baseline (speedup 1.0000x reference)
#include <cuda_runtime.h>
#include <cstdint>
#include <cstddef>
#include <math.h>

// Problem constants
#define NN 4096
#define DD 512
#define REGC 1.0f
#define INV_REG_LN2 1.4426950408889634f   // 1/(REG*ln2)
#define REG_LN2     0.6931471805599453f   // REG*ln2
#define LOG_A       (-8.317766166719343f) // -log(4096)
#define SUM_LAB     (-16.635532333438686f) // log_a + log_b
#define SHIFT_MARGIN 8.0f
#define QS      32.0f
#define INV_QS  0.03125f
#define KQ      0.045084220027780106f     // INV_REG_LN2 / 32
#define TH      34.0f                     // active-set threshold (base-2 units)
#define SCAP    96                        // entries cap per row/col

// Scratch (device globals; no allocations allowed)
__device__ unsigned short d_Mq[(size_t)NN * NN];  // 32MB quantized cost matrix
__device__ float d_f[NN], d_fs[NN];
__device__ float d_g[NN], d_gs[NN];
__device__ float d_x2[NN], d_y2[NN];
__device__ float d_rowmax[NN], d_colmax[NN];
__device__ unsigned int d_rowqmin[NN];
__device__ unsigned int d_rowcnt[NN], d_colcnt[NN];
__device__ unsigned int d_rowlist[(size_t)NN * SCAP];
__device__ unsigned int d_collist[(size_t)NN * SCAP];
__device__ double d_acc[3];

__device__ __forceinline__ float ex2f_(float x) {
    float y; asm("ex2.approx.ftz.f32 %0, %1;" : "=f"(y) : "f"(x)); return y;
}
__device__ __forceinline__ float lg2f_(float x) {
    float y; asm("lg2.approx.f32 %0, %1;" : "=f"(y) : "f"(x)); return y;
}
__device__ __forceinline__ float neg_inf_() { return __int_as_float(0xff800000); }

#define FMA2(d, a, b, c) \
    asm("fma.rn.f32x2 %0, %1, %2, %3;" : "=l"(d) : "l"(a), "l"(b), "l"(c))

__device__ __forceinline__ void lse_accum(float x, float& m, float& s) {
    float d = x - m;
    float e = ex2f_(0.f - fabsf(d));
    bool gt = d > 0.f;
    s = fmaf(s, gt ? e : 1.f, gt ? 1.f : e);
    m = gt ? x : m;
}
__device__ __forceinline__ void lse_combine(float mo, float so, float& m, float& s) {
    float mm = fmaxf(m, mo);
    s = s * ex2f_(m - mm) + so * ex2f_(mo - mm);
    m = mm;
}

// ---------------------------------------------------------------------------
__global__ void init_kernel() {
    int t = blockIdx.x * blockDim.x + threadIdx.x;
    if (t < 3) d_acc[t] = 0.0;
    if (t < NN) {
        d_g[t] = 0.f; d_gs[t] = 0.f; d_f[t] = 0.f; d_fs[t] = 0.f;
        d_rowqmin[t] = 0xffffffffu;
    }
}

__global__ void zero_cnt_kernel() {
    int t = blockIdx.x * blockDim.x + threadIdx.x;
    if (t < NN) { d_rowcnt[t] = 0u; d_colcnt[t] = 0u; }
}

// qmin -> initial row maxes (exact: g = 0 at the first f pass)
__global__ void qmax_kernel() {
    int t = blockIdx.x * blockDim.x + threadIdx.x;
    if (t < NN) d_rowmax[t] = -KQ * (float)d_rowqmin[t];
}

__global__ void norms_kernel(const float* __restrict__ X, const float* __restrict__ Y) {
    int row = blockIdx.x;
    const float* p = (row < NN) ? (X + (size_t)row * DD) : (Y + (size_t)(row - NN) * DD);
    int t = threadIdx.x;
    float4 v = ((const float4*)p)[t];
    float s = v.x * v.x + v.y * v.y + v.z * v.z + v.w * v.w;
    #pragma unroll
    for (int o = 16; o; o >>= 1) s += __shfl_down_sync(0xffffffffu, s, o);
    __shared__ float sm[4];
    if ((t & 31) == 0) sm[t >> 5] = s;
    __syncthreads();
    if (t == 0) {
        float r = sm[0] + sm[1] + sm[2] + sm[3];
        if (row < NN) d_x2[row] = r; else d_y2[row - NN] = r;
    }
}

// ---------------------------------------------------------------------------
// SGEMM with packed f32x2 FMA + duplicated-B SMEM; also records row min-q.
#define BM 128
#define BN 128
#define BK 8
__global__ void __launch_bounds__(256, 2) gemm_kernel(const float* __restrict__ X,
                                                      const float* __restrict__ Y) {
    __shared__ float As[BK][BM];                       // 4KB
    __shared__ unsigned long long Bs[BK][BN];          // 8KB (each entry = (b,b))
    __shared__ unsigned int srmin[BM];                 // row min within tile
    int tid = threadIdx.x;
    int tx = tid & 15, ty = tid >> 4;
    int bx = blockIdx.x, by = blockIdx.y;

    if (tid < BM) srmin[tid] = 0xffffu;

    int mloc = tid >> 1;
    int kq = (tid & 1) * 4;
    const float* pA = X + (size_t)(by * BM + mloc) * DD + kq;
    const float* pB = Y + (size_t)(bx * BN + mloc) * DD + kq;

    unsigned long long accp[4][8];
    #pragma unroll
    for (int p = 0; p < 4; p++)
        #pragma unroll
        for (int j = 0; j < 8; j++) accp[p][j] = 0ull;

    float4 a4 = *(const float4*)pA;
    float4 b4 = *(const float4*)pB;

    const int NKT = DD / BK;
    for (int kt = 0; kt < NKT; kt++) {
        As[kq + 0][mloc] = a4.x; As[kq + 1][mloc] = a4.y;
        As[kq + 2][mloc] = a4.z; As[kq + 3][mloc] = a4.w;
        {
            unsigned int u0 = __float_as_uint(b4.x), u1 = __float_as_uint(b4.y);
            unsigned int u2 = __float_as_uint(b4.z), u3 = __float_as_uint(b4.w);
            Bs[kq + 0][mloc] = ((unsigned long long)u0 << 32) | u0;
            Bs[kq + 1][mloc] = ((unsigned long long)u1 << 32) | u1;
            Bs[kq + 2][mloc] = ((unsigned long long)u2 << 32) | u2;
            Bs[kq + 3][mloc] = ((unsigned long long)u3 << 32) | u3;
        }
        __syncthreads();
        if (kt + 1 < NKT) {
            a4 = *(const float4*)(pA + (kt + 1) * BK);
            b4 = *(const float4*)(pB + (kt + 1) * BK);
        }
        #pragma unroll
        for (int k = 0; k < BK; k++) {
            union { float4 f; unsigned long long u[2]; } alo, ahi;
            alo.f = *(const float4*)(&As[k][ty * 8]);
            ahi.f = *(const float4*)(&As[k][ty * 8 + 4]);
            unsigned long long ap[4];
            ap[0] = alo.u[0]; ap[1] = alo.u[1];
            ap[2] = ahi.u[0]; ap[3] = ahi.u[1];
            unsigned long long bd[8];
            #pragma unroll
            for (int m = 0; m < 4; m++) {
                union { uint4 v; unsigned long long u[2]; } bw;
                bw.v = *(const uint4*)(&Bs[k][tx * 8 + 2 * m]);
                bd[2 * m] = bw.u[0]; bd[2 * m + 1] = bw.u[1];
            }
            #pragma unroll
            for (int p = 0; p < 4; p++)
                #pragma unroll
                for (int j = 0; j < 8; j++)
                    FMA2(accp[p][j], ap[p], bd[j], accp[p][j]);
        }
        __syncthreads();
    }

    int r0 = by * BM + ty * 8;
    int c0 = bx * BN + tx * 8;
    float y2v[8];
    #pragma unroll
    for (int j = 0; j < 8; j++) y2v[j] = d_y2[c0 + j];
    #pragma unroll
    for (int p = 0; p < 4; p++) {
        float x2lo = d_x2[r0 + 2 * p];
        float x2hi = d_x2[r0 + 2 * p + 1];
        unsigned short qlo[8], qhi[8];
        unsigned int rminlo = 0xffffu, rminhi = 0xffffu;
        #pragma unroll
        for (int j = 0; j < 8; j++) {
            union { unsigned long long u; unsigned int w[2]; } a;
            a.u = accp[p][j];
            float mlo = fmaxf(x2lo + y2v[j] - 2.f * __uint_as_float(a.w[0]), 0.f);
            float mhi = fmaxf(x2hi + y2v[j] - 2.f * __uint_as_float(a.w[1]), 0.f);
            unsigned int q0 = __float2uint_rn(fminf(mlo * QS, 65535.f));
            unsigned int q1 = __float2uint_rn(fminf(mhi * QS, 65535.f));
            qlo[j] = (unsigned short)q0;
            qhi[j] = (unsigned short)q1;
            rminlo = min(rminlo, q0); rminhi = min(rminhi, q1);
        }
        atomicMin(&srmin[ty * 8 + 2 * p], rminlo);
        atomicMin(&srmin[ty * 8 + 2 * p + 1], rminhi);
        unsigned short* dst = d_Mq + (size_t)(r0 + 2 * p) * NN + c0;
        *(uint4*)dst = *(uint4*)qlo;
        *(uint4*)(dst + NN) = *(uint4*)qhi;
    }
    __syncthreads();
    if (tid < BM) atomicMin(&d_rowqmin[by * BM + tid], srmin[tid]);
}

// ---------------------------------------------------------------------------
// SAFE (online) g update, records col max. grid 128 x 1024. Used once.
__global__ void __launch_bounds__(1024) g_safe_kernel() {
    __shared__ float fs[NN];
    __shared__ float pm[32][33], ps[32][33];
    int t = threadIdx.x;
    for (int j = t; j < NN; j += 1024) fs[j] = d_fs[j];
    __syncthreads();
    int lane = t & 31;
    int rg = t >> 5;
    int col = blockIdx.x * 32 + lane;
    const unsigned short* Mc = d_Mq + col;
    float m0 = neg_inf_(), m1 = neg_inf_(), m2 = neg_inf_(), m3 = neg_inf_();
    float s0 = 0.f, s1 = 0.f, s2 = 0.f, s3 = 0.f;
    for (int base = 0; base < NN; base += 128) {
        int i0 = base + rg;
        float x0 = fmaf((float)Mc[(size_t)(i0      ) * NN], -KQ, fs[i0      ]);
        float x1 = fmaf((float)Mc[(size_t)(i0 + 32 ) * NN], -KQ, fs[i0 + 32 ]);
        float x2 = fmaf((float)Mc[(size_t)(i0 + 64 ) * NN], -KQ, fs[i0 + 64 ]);
        float x3 = fmaf((float)Mc[(size_t)(i0 + 96 ) * NN], -KQ, fs[i0 + 96 ]);
        lse_accum(x0, m0, s0);
        lse_accum(x1, m1, s1);
        lse_accum(x2, m2, s2);
        lse_accum(x3, m3, s3);
    }
    lse_combine(m1, s1, m0, s0);
    lse_combine(m3, s3, m2, s2);
    lse_combine(m2, s2, m0, s0);
    pm[rg][lane] = m0; ps[rg][lane] = s0;
    __syncthreads();
    int w = t >> 5;
    float m2_ = pm[lane][w];
    float s2_ = ps[lane][w];
    #pragma unroll
    for (int o = 16; o; o >>= 1) {
        float mo = __shfl_down_sync(0xffffffffu, m2_, o);
        float so = __shfl_down_sync(0xffffffffu, s2_, o);
        float mm = fmaxf(m2_, mo);
        s2_ = s2_ * ex2f_(m2_ - mm) + so * ex2f_(mo - mm);
        m2_ = mm;
    }
    if (lane == 0) {
        float lse2 = m2_ + lg2f_(s2_);
        float gv = REGC * LOG_A - REG_LN2 * lse2;
        int c = blockIdx.x * 32 + w;
        d_g[c] = gv;
        d_gs[c] = gv * INV_REG_LN2;
        d_colmax[c] = m2_;
    }
}

// ---------------------------------------------------------------------------
// SHIFTED dense f update: 512 blocks x 512 threads, 8 rows/block.
__global__ void __launch_bounds__(512) f_shift_kernel() {
    __shared__ float gs[NN];
    __shared__ float red_s[16], red_m[16];
    int t = threadIdx.x;
    for (int j = t; j < NN; j += 512) gs[j] = d_gs[j];
    __syncthreads();
    int r = t >> 6;
    int l = t & 63;
    int row = blockIdx.x * 8 + r;
    const uint4* Mr = (const uint4*)(d_Mq + (size_t)row * NN);
    const float4* G4 = (const float4*)gs;
    float C = d_rowmax[row] + SHIFT_MARGIN;
    float s0 = 0.f, s1 = 0.f, s2 = 0.f, s3 = 0.f;
    float m0 = neg_inf_(), m1 = neg_inf_(), m2 = neg_inf_(), m3 = neg_inf_();
    #pragma unroll
    for (int k = 0; k < 8; k++) {
        int idx = l + k * 64;
        uint4 v = Mr[idx];
        float4 ga = G4[2 * idx];
        float4 gb = G4[2 * idx + 1];
        float xa = fmaf((float)(v.x & 0xffffu), -KQ, ga.x);
        float xb = fmaf((float)(v.x >> 16),    -KQ, ga.y);
        float xc = fmaf((float)(v.y & 0xffffu), -KQ, ga.z);
        float xd = fmaf((float)(v.y >> 16),    -KQ, ga.w);
        float xe = fmaf((float)(v.z & 0xffffu), -KQ, gb.x);
        float xf = fmaf((float)(v.z >> 16),    -KQ, gb.y);
        float xg = fmaf((float)(v.w & 0xffffu), -KQ, gb.z);
        float xh = fmaf((float)(v.w >> 16),    -KQ, gb.w);
        s0 += ex2f_(xa - C); m0 = fmaxf(m0, xa);
        s1 += ex2f_(xb - C); m1 = fmaxf(m1, xb);
        s2 += ex2f_(xc - C); m2 = fmaxf(m2, xc);
        s3 += ex2f_(xd - C); m3 = fmaxf(m3, xd);
        s0 += ex2f_(xe - C); m0 = fmaxf(m0, xe);
        s1 += ex2f_(xf - C); m1 = fmaxf(m1, xf);
        s2 += ex2f_(xg - C); m2 = fmaxf(m2, xg);
        s3 += ex2f_(xh - C); m3 = fmaxf(m3, xh);
    }
    float s = (s0 + s1) + (s2 + s3);
    float m = fmaxf(fmaxf(m0, m1), fmaxf(m2, m3));
    #pragma unroll
    for (int o = 16; o; o >>= 1) {
        s += __shfl_down_sync(0xffffffffu, s, o);
        m = fmaxf(m, __shfl_down_sync(0xffffffffu, m, o));
    }
    if ((t & 31) == 0) { red_s[t >> 5] = s; red_m[t >> 5] = m; }
    __syncthreads();
    if (t < 8) {
        float stot = red_s[2 * t] + red_s[2 * t + 1];
        float mtot = fmaxf(red_m[2 * t], red_m[2 * t + 1]);
        int rr = blockIdx.x * 8 + t;
        float Cr = d_rowmax[rr] + SHIFT_MARGIN;
        float lse2 = Cr + lg2f_(stot);
        float fv = REGC * LOG_A - REG_LN2 * lse2;
        d_f[rr] = fv;
        d_fs[rr] = fv * INV_REG_LN2;
        d_rowmax[rr] = mtot;
    }
}

// SHIFTED dense g update.
__global__ void __launch_bounds__(1024) g_shift_kernel() {
    __shared__ float fs[NN];
    __shared__ float pm[32][33], ps[32][33];
    int t = threadIdx.x;
    for (int j = t; j < NN; j += 1024) fs[j] = d_fs[j];
    __syncthreads();
    int lane = t & 31;
    int rg = t >> 5;
    int col = blockIdx.x * 32 + lane;
    const unsigned short* Mc = d_Mq + col;
    float C = d_colmax[col] + SHIFT_MARGIN;
    float s0 = 0.f, s1 = 0.f, s2 = 0.f, s3 = 0.f;
    float m0 = neg_inf_(), m1 = neg_inf_(), m2 = neg_inf_(), m3 = neg_inf_();
    for (int base = 0; base < NN; base += 256) {
        int i0 = base + rg;
        unsigned short a0 = Mc[(size_t)(i0       ) * NN];
        unsigned short a1 = Mc[(size_t)(i0 + 32  ) * NN];
        unsigned short a2 = Mc[(size_t)(i0 + 64  ) * NN];
        unsigned short a3 = Mc[(size_t)(i0 + 96  ) * NN];
        unsigned short a4 = Mc[(size_t)(i0 + 128 ) * NN];
        unsigned short a5 = Mc[(size_t)(i0 + 160 ) * NN];
        unsigned short a6 = Mc[(size_t)(i0 + 192 ) * NN];
        unsigned short a7 = Mc[(size_t)(i0 + 224 ) * NN];
        float x0 = fmaf((float)a0, -KQ, fs[i0      ]);
        float x1 = fmaf((float)a1, -KQ, fs[i0 + 32 ]);
        float x2 = fmaf((float)a2, -KQ, fs[i0 + 64 ]);
        float x3 = fmaf((float)a3, -KQ, fs[i0 + 96 ]);
        float x4 = fmaf((float)a4, -KQ, fs[i0 + 128]);
        float x5 = fmaf((float)a5, -KQ, fs[i0 + 160]);
        float x6 = fmaf((float)a6, -KQ, fs[i0 + 192]);
        float x7 = fmaf((float)a7, -KQ, fs[i0 + 224]);
        s0 += ex2f_(x0 - C); m0 = fmaxf(m0, x0);
        s1 += ex2f_(x1 - C); m1 = fmaxf(m1, x1);
        s2 += ex2f_(x2 - C); m2 = fmaxf(m2, x2);
        s3 += ex2f_(x3 - C); m3 = fmaxf(m3, x3);
        s0 += ex2f_(x4 - C); m0 = fmaxf(m0, x4);
        s1 += ex2f_(x5 - C); m1 = fmaxf(m1, x5);
        s2 += ex2f_(x6 - C); m2 = fmaxf(m2, x6);
        s3 += ex2f_(x7 - C); m3 = fmaxf(m3, x7);
    }
    ps[rg][lane] = (s0 + s1) + (s2 + s3);
    pm[rg][lane] = fmaxf(fmaxf(m0, m1), fmaxf(m2, m3));
    __syncthreads();
    int w = t >> 5;
    float s2_ = ps[lane][w];
    float m2_ = pm[lane][w];
    #pragma unroll
    for (int o = 16; o; o >>= 1) {
        s2_ += __shfl_down_sync(0xffffffffu, s2_, o);
        m2_ = fmaxf(m2_, __shfl_down_sync(0xffffffffu, m2_, o));
    }
    if (lane == 0) {
        int c = blockIdx.x * 32 + w;
        float Cc = d_colmax[c] + SHIFT_MARGIN;
        float lse2 = Cc + lg2f_(s2_);
        float gv = REGC * LOG_A - REG_LN2 * lse2;
        d_g[c] = gv;
        d_gs[c] = gv * INV_REG_LN2;
        d_colmax[c] = m2_;
    }
}

// ---------------------------------------------------------------------------
// BUILD: scan Mq once; collect active entries per row and per column.
__global__ void __launch_bounds__(256) build_kernel() {
    __shared__ float gsm[NN];
    __shared__ float cth[NN];
    int t = threadIdx.x;
    for (int k = t; k < NN; k += 256) {
        gsm[k] = d_gs[k];
        cth[k] = d_colmax[k] - TH;
    }
    __syncthreads();
    int row0 = blockIdx.x * 16;
    for (int r = 0; r < 16; r++) {
        int row = row0 + r;
        float rth = d_rowmax[row] - TH;
        float fsv = d_fs[row];
        const uint4* Mr = (const uint4*)(d_Mq + (size_t)row * NN);
        for (int idx = t; idx < NN / 8; idx += 256) {
            uint4 v = Mr[idx];
            int j0 = idx * 8;
            unsigned int qs[8];
            qs[0] = v.x & 0xffffu; qs[1] = v.x >> 16;
            qs[2] = v.y & 0xffffu; qs[3] = v.y >> 16;
            qs[4] = v.z & 0xffffu; qs[5] = v.z >> 16;
            qs[6] = v.w & 0xffffu; qs[7] = v.w >> 16;
            #pragma unroll
            for (int h = 0; h < 8; h++) {
                int j = j0 + h;
                float qf = (float)qs[h];
                float xr = fmaf(qf, -KQ, gsm[j]);
                if (xr >= rth) {
                    unsigned int p = atomicAdd(&d_rowcnt[row], 1u);
                    if (p < SCAP) d_rowlist[(size_t)row * SCAP + p] = ((unsigned int)j << 16) | qs[h];
                }
                float xc = fmaf(qf, -KQ, fsv);
                if (xc >= cth[j]) {
                    unsigned int p = atomicAdd(&d_colcnt[j], 1u);
                    if (p < SCAP) d_collist[(size_t)j * SCAP + p] = ((unsigned int)row << 16) | qs[h];
                }
            }
        }
    }
}

// ---------------------------------------------------------------------------
// SPARSE Sinkhorn: cluster of 8 CTAs x 512 threads; thread-per-row/col.
__global__ void __launch_bounds__(512) __cluster_dims__(8, 1, 1)
sparse_kernel(int npairs) {
    __shared__ float vsh[NN];
    int t = threadIdx.x;
    int id = blockIdx.x * 512 + t;

    int nr = (int)d_rowcnt[id]; if (nr > SCAP) nr = SCAP;
    int nc = (int)d_colcnt[id]; if (nc > SCAP) nc = SCAP;
    const unsigned int* rlp = d_rowlist + (size_t)id * SCAP;
    const unsigned int* clp = d_collist + (size_t)id * SCAP;

    for (int it = 0; it < npairs; it++) {
        for (int k = t; k < NN; k += 512) vsh[k] = __ldcg(&d_gs[k]);
        __syncthreads();
        {
            float m = neg_inf_(), s = 0.f;
            for (int k = 0; k < nr; k++) {
                unsigned int e = rlp[k];
                float x = fmaf((float)(e & 0xffffu), -KQ, vsh[e >> 16]);
                lse_accum(x, m, s);
            }
            float lse2 = m + lg2f_(s);
            float fv = REGC * LOG_A - REG_LN2 * lse2;
            d_f[id] = fv;
            d_fs[id] = fv * INV_REG_LN2;
            d_rowmax[id] = m;
        }
        __threadfence();
        __syncthreads();
        asm volatile("barrier.cluster.arrive.aligned;" ::: "memory");
        asm volatile("barrier.cluster.wait.aligned;" ::: "memory");

        for (int k = t; k < NN; k += 512) vsh[k] = __ldcg(&d_fs[k]);
        __syncthreads();
        {
            float m = neg_inf_(), s = 0.f;
            for (int k = 0; k < nc; k++) {
                unsigned int e = clp[k];
                float x = fmaf((float)(e & 0xffffu), -KQ, vsh[e >> 16]);
                lse_accum(x, m, s);
            }
            float lse2 = m + lg2f_(s);
            float gv = REGC * LOG_A - REG_LN2 * lse2;   // log_b == log_a
            d_g[id] = gv;
            d_gs[id] = gv * INV_REG_LN2;
            d_colmax[id] = m;
        }
        __threadfence();
        __syncthreads();
        asm volatile("barrier.cluster.arrive.aligned;" ::: "memory");
        asm volatile("barrier.cluster.wait.aligned;" ::: "memory");
    }
}

// ---------------------------------------------------------------------------
// Final reduction: S1 = sum P*M, S2 = sum P*logP, S3 = sum P (dense, exact)
__global__ void __launch_bounds__(256) final_kernel() {
    __shared__ float gsh[NN];
    __shared__ float r1[8], r2[8], r3[8];
    int t = threadIdx.x;
    for (int j = t; j < NN; j += 256) gsh[j] = d_g[j];
    __syncthreads();
    const float4* g4 = (const float4*)gsh;
    int row0 = blockIdx.x * 4;
    float S1 = 0.f, S2 = 0.f, S3 = 0.f;
    for (int r = 0; r < 4; r++) {
        float fi = d_f[row0 + r];
        const uint2* Mr = (const uint2*)(d_Mq + (size_t)(row0 + r) * NN);
        #pragma unroll
        for (int j = t; j < NN / 4; j += 256) {
            uint2 v = Mr[j];
            float4 gv = g4[j];
            float M0 = (float)(v.x & 0xffffu) * INV_QS;
            float M1 = (float)(v.x >> 16)    * INV_QS;
            float M2 = (float)(v.y & 0xffffu) * INV_QS;
            float M3 = (float)(v.y >> 16)    * INV_QS;
            float lp0 = (fi + gv.x - M0);
            float lp1 = (fi + gv.y - M1);
            float lp2 = (fi + gv.z - M2);
            float lp3 = (fi + gv.w - M3);
            float p0 = ex2f_(lp0 * INV_REG_LN2);
            float p1 = ex2f_(lp1 * INV_REG_LN2);
            float p2 = ex2f_(lp2 * INV_REG_LN2);
            float p3 = ex2f_(lp3 * INV_REG_LN2);
            S1 = fmaf(p0, M0, fmaf(p1, M1, fmaf(p2, M2, fmaf(p3, M3, S1))));
            S2 = fmaf(p0, lp0, fmaf(p1, lp1, fmaf(p2, lp2, fmaf(p3, lp3, S2))));
            S3 += (p0 + p1) + (p2 + p3);
        }
    }
    #pragma unroll
    for (int o = 16; o; o >>= 1) {
        S1 += __shfl_down_sync(0xffffffffu, S1, o);
        S2 += __shfl_down_sync(0xffffffffu, S2, o);
        S3 += __shfl_down_sync(0xffffffffu, S3, o);
    }
    if ((t & 31) == 0) { r1[t >> 5] = S1; r2[t >> 5] = S2; r3[t >> 5] = S3; }
    __syncthreads();
    if (t == 0) {
        double a1 = 0, a2 = 0, a3 = 0;
        for (int w = 0; w < 8; w++) { a1 += r1[w]; a2 += r2[w]; a3 += r3[w]; }
        atomicAdd(&d_acc[0], a1);
        atomicAdd(&d_acc[1], a2);
        atomicAdd(&d_acc[2], a3);
    }
}

__global__ void finalize_kernel(float* out) {
    double S1 = d_acc[0], S2 = d_acc[1], S3 = d_acc[2];
    double v = S1 + (double)REGC * (S2 - (double)SUM_LAB * S3 - S3 + 1.0);
    out[0] = (float)v;
}

// ---------------------------------------------------------------------------
extern "C" void kernel_launch(void* const* d_in, const int* in_sizes, int n_in,
                              void* d_out, int out_size) {
    const float* X = (const float*)d_in[0];   // source [4096,512]
    const float* Y = (const float*)d_in[1];   // target [4096,512]

    init_kernel<<<16, 256>>>();
    norms_kernel<<<2 * NN, 128>>>(X, Y);
    dim3 gg(NN / BN, NN / BM);
    gemm_kernel<<<gg, 256>>>(X, Y);
    qmax_kernel<<<16, 256>>>();

    // Pair 1: f via shift (row maxes seeded exactly: g == 0), g via safe online
    f_shift_kernel<<<512, 512>>>();
    g_safe_kernel<<<128, 1024>>>();
    // Pairs 2..12: both shifted
    for (int it = 0; it < 11; it++) {
        f_shift_kernel<<<512, 512>>>();
        g_shift_kernel<<<128, 1024>>>();
    }

    // Sparse phase: 88 pairs in 3 segments with list rebuilds
    zero_cnt_kernel<<<16, 256>>>();
    build_kernel<<<256, 256>>>();
    sparse_kernel<<<8, 512>>>(30);

    zero_cnt_kernel<<<16, 256>>>();
    build_kernel<<<256, 256>>>();
    sparse_kernel<<<8, 512>>>(30);

    zero_cnt_kernel<<<16, 256>>>();
    build_kernel<<<256, 256>>>();
    sparse_kernel<<<8, 512>>>(28);

    final_kernel<<<1024, 256>>>();
    finalize_kernel<<<1, 1>>>((float*)d_out);
}

// round 13
// speedup vs baseline: 2.1663x; 2.1663x over previous
#include <cuda_runtime.h>
#include <cstdint>
#include <cstddef>
#include <math.h>

// Problem constants
#define NN 4096
#define DD 512
#define REGC 1.0f
#define INV_REG_LN2 1.4426950408889634f   // 1/(REG*ln2)
#define REG_LN2     0.6931471805599453f   // REG*ln2
#define LOG_A       (-8.317766166719343f) // -log(4096)
#define SUM_LAB     (-16.635532333438686f) // log_a + log_b
#define SHIFT_MARGIN 8.0f
#define QS      32.0f
#define INV_QS  0.03125f
#define KQ      0.045084220027780106f     // INV_REG_LN2 / 32
#define TH      34.0f                     // active-set threshold (base-2 units)
#define SCAP    96                        // entries cap per row/col

// Scratch (device globals; no allocations allowed)
__device__ unsigned short d_Mq[(size_t)NN * NN];  // 32MB quantized cost matrix
__device__ float d_f[NN], d_fs[NN];
__device__ float d_g[NN], d_gs[NN];
__device__ float d_x2[NN], d_y2[NN];
__device__ float d_rowmax[NN], d_colmax[NN];
__device__ unsigned int d_rowqmin[NN];
__device__ unsigned int d_rowcnt[NN], d_colcnt[NN];
__device__ unsigned int d_rowlist[(size_t)NN * SCAP];
__device__ unsigned int d_collist[(size_t)NN * SCAP];
__device__ double d_acc[3];

__device__ __forceinline__ float ex2f_(float x) {
    float y; asm("ex2.approx.ftz.f32 %0, %1;" : "=f"(y) : "f"(x)); return y;
}
__device__ __forceinline__ float lg2f_(float x) {
    float y; asm("lg2.approx.f32 %0, %1;" : "=f"(y) : "f"(x)); return y;
}
__device__ __forceinline__ float neg_inf_() { return __int_as_float(0xff800000); }

#define FMA2(d, a, b, c) \
    asm("fma.rn.f32x2 %0, %1, %2, %3;" : "=l"(d) : "l"(a), "l"(b), "l"(c))
#define DUP_F32X2(r, f) \
    asm("mov.b64 %0, {%1, %1};" : "=l"(r) : "r"(f))
#define UNPACK2(lo, hi, v) \
    asm("mov.b64 {%0, %1}, %2;" : "=r"(lo), "=r"(hi) : "l"(v))

__device__ __forceinline__ void lse_accum(float x, float& m, float& s) {
    float d = x - m;
    float e = ex2f_(0.f - fabsf(d));
    bool gt = d > 0.f;
    s = fmaf(s, gt ? e : 1.f, gt ? 1.f : e);
    m = gt ? x : m;
}
__device__ __forceinline__ void lse_combine(float mo, float so, float& m, float& s) {
    float mm = fmaxf(m, mo);
    s = s * ex2f_(m - mm) + so * ex2f_(mo - mm);
    m = mm;
}

// ---------------------------------------------------------------------------
__global__ void init_kernel() {
    int t = blockIdx.x * blockDim.x + threadIdx.x;
    if (t < 3) d_acc[t] = 0.0;
    if (t < NN) {
        d_g[t] = 0.f; d_gs[t] = 0.f; d_f[t] = 0.f; d_fs[t] = 0.f;
        d_rowqmin[t] = 0xffffffffu;
    }
}

__global__ void zero_cnt_kernel() {
    int t = blockIdx.x * blockDim.x + threadIdx.x;
    if (t < NN) { d_rowcnt[t] = 0u; d_colcnt[t] = 0u; }
}

// qmin -> initial row maxes (exact: g = 0 at the first f pass)
__global__ void qmax_kernel() {
    int t = blockIdx.x * blockDim.x + threadIdx.x;
    if (t < NN) d_rowmax[t] = -KQ * (float)d_rowqmin[t];
}

__global__ void norms_kernel(const float* __restrict__ X, const float* __restrict__ Y) {
    int row = blockIdx.x;
    const float* p = (row < NN) ? (X + (size_t)row * DD) : (Y + (size_t)(row - NN) * DD);
    int t = threadIdx.x;
    float4 v = ((const float4*)p)[t];
    float s = v.x * v.x + v.y * v.y + v.z * v.z + v.w * v.w;
    #pragma unroll
    for (int o = 16; o; o >>= 1) s += __shfl_down_sync(0xffffffffu, s, o);
    __shared__ float sm[4];
    if ((t & 31) == 0) sm[t >> 5] = s;
    __syncthreads();
    if (t == 0) {
        float r = sm[0] + sm[1] + sm[2] + sm[3];
        if (row < NN) d_x2[row] = r; else d_y2[row - NN] = r;
    }
}

// ---------------------------------------------------------------------------
// SGEMM with packed f32x2 FMA (R8 proven inner loop) + row min-q tracking.
#define BM 128
#define BN 128
#define BK 8
__global__ void __launch_bounds__(256, 2) gemm_kernel(const float* __restrict__ X,
                                                      const float* __restrict__ Y) {
    __shared__ float As[BK][BM];
    __shared__ float Bs[BK][BN];
    __shared__ unsigned int srmin[BM];
    int tid = threadIdx.x;
    int tx = tid & 15, ty = tid >> 4;
    int bx = blockIdx.x, by = blockIdx.y;

    if (tid < BM) srmin[tid] = 0xffffu;

    int mloc = tid >> 1;
    int kq = (tid & 1) * 4;
    const float* pA = X + (size_t)(by * BM + mloc) * DD + kq;
    const float* pB = Y + (size_t)(bx * BN + mloc) * DD + kq;

    // accp[p][j] packs rows (2p, 2p+1) for column j
    unsigned long long accp[4][8];
    #pragma unroll
    for (int p = 0; p < 4; p++)
        #pragma unroll
        for (int j = 0; j < 8; j++) accp[p][j] = 0ull;

    float4 a4 = *(const float4*)pA;
    float4 b4 = *(const float4*)pB;

    const int NKT = DD / BK;
    for (int kt = 0; kt < NKT; kt++) {
        As[kq + 0][mloc] = a4.x; As[kq + 1][mloc] = a4.y;
        As[kq + 2][mloc] = a4.z; As[kq + 3][mloc] = a4.w;
        Bs[kq + 0][mloc] = b4.x; Bs[kq + 1][mloc] = b4.y;
        Bs[kq + 2][mloc] = b4.z; Bs[kq + 3][mloc] = b4.w;
        __syncthreads();
        if (kt + 1 < NKT) {
            a4 = *(const float4*)(pA + (kt + 1) * BK);
            b4 = *(const float4*)(pB + (kt + 1) * BK);
        }
        #pragma unroll
        for (int k = 0; k < BK; k++) {
            unsigned long long ap[4];
            #pragma unroll
            for (int p = 0; p < 4; p++)
                ap[p] = *(const unsigned long long*)(&As[k][ty * 8 + 2 * p]);
            float bl[8];
            *(float4*)(&bl[0]) = *(const float4*)(&Bs[k][tx * 8]);
            *(float4*)(&bl[4]) = *(const float4*)(&Bs[k][tx * 8 + 4]);
            unsigned long long bd[8];
            #pragma unroll
            for (int j = 0; j < 8; j++) DUP_F32X2(bd[j], __float_as_uint(bl[j]));
            #pragma unroll
            for (int p = 0; p < 4; p++)
                #pragma unroll
                for (int j = 0; j < 8; j++)
                    FMA2(accp[p][j], ap[p], bd[j], accp[p][j]);
        }
        __syncthreads();
    }

    int r0 = by * BM + ty * 8;
    int c0 = bx * BN + tx * 8;
    float y2v[8];
    #pragma unroll
    for (int j = 0; j < 8; j++) y2v[j] = d_y2[c0 + j];
    #pragma unroll
    for (int p = 0; p < 4; p++) {
        float x2lo = d_x2[r0 + 2 * p];
        float x2hi = d_x2[r0 + 2 * p + 1];
        unsigned short qlo[8], qhi[8];
        unsigned int rminlo = 0xffffu, rminhi = 0xffffu;
        #pragma unroll
        for (int j = 0; j < 8; j++) {
            unsigned int ulo, uhi;
            UNPACK2(ulo, uhi, accp[p][j]);
            float mlo = fmaxf(x2lo + y2v[j] - 2.f * __uint_as_float(ulo), 0.f);
            float mhi = fmaxf(x2hi + y2v[j] - 2.f * __uint_as_float(uhi), 0.f);
            unsigned int q0 = __float2uint_rn(fminf(mlo * QS, 65535.f));
            unsigned int q1 = __float2uint_rn(fminf(mhi * QS, 65535.f));
            qlo[j] = (unsigned short)q0;
            qhi[j] = (unsigned short)q1;
            rminlo = min(rminlo, q0); rminhi = min(rminhi, q1);
        }
        atomicMin(&srmin[ty * 8 + 2 * p], rminlo);
        atomicMin(&srmin[ty * 8 + 2 * p + 1], rminhi);
        unsigned short* dst = d_Mq + (size_t)(r0 + 2 * p) * NN + c0;
        *(uint4*)dst = *(uint4*)qlo;
        *(uint4*)(dst + NN) = *(uint4*)qhi;
    }
    __syncthreads();
    if (tid < BM) atomicMin(&d_rowqmin[by * BM + tid], srmin[tid]);
}

// ---------------------------------------------------------------------------
// SAFE (online) g update, records col max. grid 128 x 1024. Used once.
__global__ void __launch_bounds__(1024) g_safe_kernel() {
    __shared__ float fs[NN];
    __shared__ float pm[32][33], ps[32][33];
    int t = threadIdx.x;
    for (int j = t; j < NN; j += 1024) fs[j] = d_fs[j];
    __syncthreads();
    int lane = t & 31;
    int rg = t >> 5;
    int col = blockIdx.x * 32 + lane;
    const unsigned short* Mc = d_Mq + col;
    float m0 = neg_inf_(), m1 = neg_inf_(), m2 = neg_inf_(), m3 = neg_inf_();
    float s0 = 0.f, s1 = 0.f, s2 = 0.f, s3 = 0.f;
    for (int base = 0; base < NN; base += 128) {
        int i0 = base + rg;
        float x0 = fmaf((float)Mc[(size_t)(i0      ) * NN], -KQ, fs[i0      ]);
        float x1 = fmaf((float)Mc[(size_t)(i0 + 32 ) * NN], -KQ, fs[i0 + 32 ]);
        float x2 = fmaf((float)Mc[(size_t)(i0 + 64 ) * NN], -KQ, fs[i0 + 64 ]);
        float x3 = fmaf((float)Mc[(size_t)(i0 + 96 ) * NN], -KQ, fs[i0 + 96 ]);
        lse_accum(x0, m0, s0);
        lse_accum(x1, m1, s1);
        lse_accum(x2, m2, s2);
        lse_accum(x3, m3, s3);
    }
    lse_combine(m1, s1, m0, s0);
    lse_combine(m3, s3, m2, s2);
    lse_combine(m2, s2, m0, s0);
    pm[rg][lane] = m0; ps[rg][lane] = s0;
    __syncthreads();
    int w = t >> 5;
    float m2_ = pm[lane][w];
    float s2_ = ps[lane][w];
    #pragma unroll
    for (int o = 16; o; o >>= 1) {
        float mo = __shfl_down_sync(0xffffffffu, m2_, o);
        float so = __shfl_down_sync(0xffffffffu, s2_, o);
        float mm = fmaxf(m2_, mo);
        s2_ = s2_ * ex2f_(m2_ - mm) + so * ex2f_(mo - mm);
        m2_ = mm;
    }
    if (lane == 0) {
        float lse2 = m2_ + lg2f_(s2_);
        float gv = REGC * LOG_A - REG_LN2 * lse2;
        int c = blockIdx.x * 32 + w;
        d_g[c] = gv;
        d_gs[c] = gv * INV_REG_LN2;
        d_colmax[c] = m2_;
    }
}

// ---------------------------------------------------------------------------
// SHIFTED dense f update: 512 blocks x 512 threads, 8 rows/block.
__global__ void __launch_bounds__(512) f_shift_kernel() {
    __shared__ float gs[NN];
    __shared__ float red_s[16], red_m[16];
    int t = threadIdx.x;
    for (int j = t; j < NN; j += 512) gs[j] = d_gs[j];
    __syncthreads();
    int r = t >> 6;
    int l = t & 63;
    int row = blockIdx.x * 8 + r;
    const uint4* Mr = (const uint4*)(d_Mq + (size_t)row * NN);
    const float4* G4 = (const float4*)gs;
    float C = d_rowmax[row] + SHIFT_MARGIN;
    float s0 = 0.f, s1 = 0.f, s2 = 0.f, s3 = 0.f;
    float m0 = neg_inf_(), m1 = neg_inf_(), m2 = neg_inf_(), m3 = neg_inf_();
    #pragma unroll
    for (int k = 0; k < 8; k++) {
        int idx = l + k * 64;
        uint4 v = Mr[idx];
        float4 ga = G4[2 * idx];
        float4 gb = G4[2 * idx + 1];
        float xa = fmaf((float)(v.x & 0xffffu), -KQ, ga.x);
        float xb = fmaf((float)(v.x >> 16),    -KQ, ga.y);
        float xc = fmaf((float)(v.y & 0xffffu), -KQ, ga.z);
        float xd = fmaf((float)(v.y >> 16),    -KQ, ga.w);
        float xe = fmaf((float)(v.z & 0xffffu), -KQ, gb.x);
        float xf = fmaf((float)(v.z >> 16),    -KQ, gb.y);
        float xg = fmaf((float)(v.w & 0xffffu), -KQ, gb.z);
        float xh = fmaf((float)(v.w >> 16),    -KQ, gb.w);
        s0 += ex2f_(xa - C); m0 = fmaxf(m0, xa);
        s1 += ex2f_(xb - C); m1 = fmaxf(m1, xb);
        s2 += ex2f_(xc - C); m2 = fmaxf(m2, xc);
        s3 += ex2f_(xd - C); m3 = fmaxf(m3, xd);
        s0 += ex2f_(xe - C); m0 = fmaxf(m0, xe);
        s1 += ex2f_(xf - C); m1 = fmaxf(m1, xf);
        s2 += ex2f_(xg - C); m2 = fmaxf(m2, xg);
        s3 += ex2f_(xh - C); m3 = fmaxf(m3, xh);
    }
    float s = (s0 + s1) + (s2 + s3);
    float m = fmaxf(fmaxf(m0, m1), fmaxf(m2, m3));
    #pragma unroll
    for (int o = 16; o; o >>= 1) {
        s += __shfl_down_sync(0xffffffffu, s, o);
        m = fmaxf(m, __shfl_down_sync(0xffffffffu, m, o));
    }
    if ((t & 31) == 0) { red_s[t >> 5] = s; red_m[t >> 5] = m; }
    __syncthreads();
    if (t < 8) {
        float stot = red_s[2 * t] + red_s[2 * t + 1];
        float mtot = fmaxf(red_m[2 * t], red_m[2 * t + 1]);
        int rr = blockIdx.x * 8 + t;
        float Cr = d_rowmax[rr] + SHIFT_MARGIN;
        float lse2 = Cr + lg2f_(stot);
        float fv = REGC * LOG_A - REG_LN2 * lse2;
        d_f[rr] = fv;
        d_fs[rr] = fv * INV_REG_LN2;
        d_rowmax[rr] = mtot;
    }
}

// SHIFTED dense g update.
__global__ void __launch_bounds__(1024) g_shift_kernel() {
    __shared__ float fs[NN];
    __shared__ float pm[32][33], ps[32][33];
    int t = threadIdx.x;
    for (int j = t; j < NN; j += 1024) fs[j] = d_fs[j];
    __syncthreads();
    int lane = t & 31;
    int rg = t >> 5;
    int col = blockIdx.x * 32 + lane;
    const unsigned short* Mc = d_Mq + col;
    float C = d_colmax[col] + SHIFT_MARGIN;
    float s0 = 0.f, s1 = 0.f, s2 = 0.f, s3 = 0.f;
    float m0 = neg_inf_(), m1 = neg_inf_(), m2 = neg_inf_(), m3 = neg_inf_();
    for (int base = 0; base < NN; base += 256) {
        int i0 = base + rg;
        unsigned short a0 = Mc[(size_t)(i0       ) * NN];
        unsigned short a1 = Mc[(size_t)(i0 + 32  ) * NN];
        unsigned short a2 = Mc[(size_t)(i0 + 64  ) * NN];
        unsigned short a3 = Mc[(size_t)(i0 + 96  ) * NN];
        unsigned short a4 = Mc[(size_t)(i0 + 128 ) * NN];
        unsigned short a5 = Mc[(size_t)(i0 + 160 ) * NN];
        unsigned short a6 = Mc[(size_t)(i0 + 192 ) * NN];
        unsigned short a7 = Mc[(size_t)(i0 + 224 ) * NN];
        float x0 = fmaf((float)a0, -KQ, fs[i0      ]);
        float x1 = fmaf((float)a1, -KQ, fs[i0 + 32 ]);
        float x2 = fmaf((float)a2, -KQ, fs[i0 + 64 ]);
        float x3 = fmaf((float)a3, -KQ, fs[i0 + 96 ]);
        float x4 = fmaf((float)a4, -KQ, fs[i0 + 128]);
        float x5 = fmaf((float)a5, -KQ, fs[i0 + 160]);
        float x6 = fmaf((float)a6, -KQ, fs[i0 + 192]);
        float x7 = fmaf((float)a7, -KQ, fs[i0 + 224]);
        s0 += ex2f_(x0 - C); m0 = fmaxf(m0, x0);
        s1 += ex2f_(x1 - C); m1 = fmaxf(m1, x1);
        s2 += ex2f_(x2 - C); m2 = fmaxf(m2, x2);
        s3 += ex2f_(x3 - C); m3 = fmaxf(m3, x3);
        s0 += ex2f_(x4 - C); m0 = fmaxf(m0, x4);
        s1 += ex2f_(x5 - C); m1 = fmaxf(m1, x5);
        s2 += ex2f_(x6 - C); m2 = fmaxf(m2, x6);
        s3 += ex2f_(x7 - C); m3 = fmaxf(m3, x7);
    }
    ps[rg][lane] = (s0 + s1) + (s2 + s3);
    pm[rg][lane] = fmaxf(fmaxf(m0, m1), fmaxf(m2, m3));
    __syncthreads();
    int w = t >> 5;
    float s2_ = ps[lane][w];
    float m2_ = pm[lane][w];
    #pragma unroll
    for (int o = 16; o; o >>= 1) {
        s2_ += __shfl_down_sync(0xffffffffu, s2_, o);
        m2_ = fmaxf(m2_, __shfl_down_sync(0xffffffffu, m2_, o));
    }
    if (lane == 0) {
        int c = blockIdx.x * 32 + w;
        float Cc = d_colmax[c] + SHIFT_MARGIN;
        float lse2 = Cc + lg2f_(s2_);
        float gv = REGC * LOG_A - REG_LN2 * lse2;
        d_g[c] = gv;
        d_gs[c] = gv * INV_REG_LN2;
        d_colmax[c] = m2_;
    }
}

// ---------------------------------------------------------------------------
// BUILD: scan Mq once; collect active entries per row and per column.
__global__ void __launch_bounds__(256) build_kernel() {
    __shared__ float gsm[NN];
    __shared__ float cth[NN];
    int t = threadIdx.x;
    for (int k = t; k < NN; k += 256) {
        gsm[k] = d_gs[k];
        cth[k] = d_colmax[k] - TH;
    }
    __syncthreads();
    int row0 = blockIdx.x * 16;
    for (int r = 0; r < 16; r++) {
        int row = row0 + r;
        float rth = d_rowmax[row] - TH;
        float fsv = d_fs[row];
        const uint4* Mr = (const uint4*)(d_Mq + (size_t)row * NN);
        for (int idx = t; idx < NN / 8; idx += 256) {
            uint4 v = Mr[idx];
            int j0 = idx * 8;
            unsigned int qs[8];
            qs[0] = v.x & 0xffffu; qs[1] = v.x >> 16;
            qs[2] = v.y & 0xffffu; qs[3] = v.y >> 16;
            qs[4] = v.z & 0xffffu; qs[5] = v.z >> 16;
            qs[6] = v.w & 0xffffu; qs[7] = v.w >> 16;
            #pragma unroll
            for (int h = 0; h < 8; h++) {
                int j = j0 + h;
                float qf = (float)qs[h];
                float xr = fmaf(qf, -KQ, gsm[j]);
                if (xr >= rth) {
                    unsigned int p = atomicAdd(&d_rowcnt[row], 1u);
                    if (p < SCAP) d_rowlist[(size_t)row * SCAP + p] = ((unsigned int)j << 16) | qs[h];
                }
                float xc = fmaf(qf, -KQ, fsv);
                if (xc >= cth[j]) {
                    unsigned int p = atomicAdd(&d_colcnt[j], 1u);
                    if (p < SCAP) d_collist[(size_t)j * SCAP + p] = ((unsigned int)row << 16) | qs[h];
                }
            }
        }
    }
}

// ---------------------------------------------------------------------------
// SPARSE Sinkhorn: cluster of 8 CTAs x 512 threads; thread-per-row/col.
__global__ void __launch_bounds__(512) __cluster_dims__(8, 1, 1)
sparse_kernel(int npairs) {
    __shared__ float vsh[NN];
    int t = threadIdx.x;
    int id = blockIdx.x * 512 + t;

    int nr = (int)d_rowcnt[id]; if (nr > SCAP) nr = SCAP;
    int nc = (int)d_colcnt[id]; if (nc > SCAP) nc = SCAP;
    const unsigned int* rlp = d_rowlist + (size_t)id * SCAP;
    const unsigned int* clp = d_collist + (size_t)id * SCAP;

    for (int it = 0; it < npairs; it++) {
        for (int k = t; k < NN; k += 512) vsh[k] = __ldcg(&d_gs[k]);
        __syncthreads();
        {
            float m = neg_inf_(), s = 0.f;
            for (int k = 0; k < nr; k++) {
                unsigned int e = rlp[k];
                float x = fmaf((float)(e & 0xffffu), -KQ, vsh[e >> 16]);
                lse_accum(x, m, s);
            }
            float lse2 = m + lg2f_(s);
            float fv = REGC * LOG_A - REG_LN2 * lse2;
            d_f[id] = fv;
            d_fs[id] = fv * INV_REG_LN2;
            d_rowmax[id] = m;
        }
        __threadfence();
        __syncthreads();
        asm volatile("barrier.cluster.arrive.aligned;" ::: "memory");
        asm volatile("barrier.cluster.wait.aligned;" ::: "memory");

        for (int k = t; k < NN; k += 512) vsh[k] = __ldcg(&d_fs[k]);
        __syncthreads();
        {
            float m = neg_inf_(), s = 0.f;
            for (int k = 0; k < nc; k++) {
                unsigned int e = clp[k];
                float x = fmaf((float)(e & 0xffffu), -KQ, vsh[e >> 16]);
                lse_accum(x, m, s);
            }
            float lse2 = m + lg2f_(s);
            float gv = REGC * LOG_A - REG_LN2 * lse2;   // log_b == log_a
            d_g[id] = gv;
            d_gs[id] = gv * INV_REG_LN2;
            d_colmax[id] = m;
        }
        __threadfence();
        __syncthreads();
        asm volatile("barrier.cluster.arrive.aligned;" ::: "memory");
        asm volatile("barrier.cluster.wait.aligned;" ::: "memory");
    }
}

// ---------------------------------------------------------------------------
// Final reduction: S1 = sum P*M, S2 = sum P*logP, S3 = sum P (dense, exact)
__global__ void __launch_bounds__(256) final_kernel() {
    __shared__ float gsh[NN];
    __shared__ float r1[8], r2[8], r3[8];
    int t = threadIdx.x;
    for (int j = t; j < NN; j += 256) gsh[j] = d_g[j];
    __syncthreads();
    const float4* g4 = (const float4*)gsh;
    int row0 = blockIdx.x * 4;
    float S1 = 0.f, S2 = 0.f, S3 = 0.f;
    for (int r = 0; r < 4; r++) {
        float fi = d_f[row0 + r];
        const uint2* Mr = (const uint2*)(d_Mq + (size_t)(row0 + r) * NN);
        #pragma unroll
        for (int j = t; j < NN / 4; j += 256) {
            uint2 v = Mr[j];
            float4 gv = g4[j];
            float M0 = (float)(v.x & 0xffffu) * INV_QS;
            float M1 = (float)(v.x >> 16)    * INV_QS;
            float M2 = (float)(v.y & 0xffffu) * INV_QS;
            float M3 = (float)(v.y >> 16)    * INV_QS;
            float lp0 = (fi + gv.x - M0);
            float lp1 = (fi + gv.y - M1);
            float lp2 = (fi + gv.z - M2);
            float lp3 = (fi + gv.w - M3);
            float p0 = ex2f_(lp0 * INV_REG_LN2);
            float p1 = ex2f_(lp1 * INV_REG_LN2);
            float p2 = ex2f_(lp2 * INV_REG_LN2);
            float p3 = ex2f_(lp3 * INV_REG_LN2);
            S1 = fmaf(p0, M0, fmaf(p1, M1, fmaf(p2, M2, fmaf(p3, M3, S1))));
            S2 = fmaf(p0, lp0, fmaf(p1, lp1, fmaf(p2, lp2, fmaf(p3, lp3, S2))));
            S3 += (p0 + p1) + (p2 + p3);
        }
    }
    #pragma unroll
    for (int o = 16; o; o >>= 1) {
        S1 += __shfl_down_sync(0xffffffffu, S1, o);
        S2 += __shfl_down_sync(0xffffffffu, S2, o);
        S3 += __shfl_down_sync(0xffffffffu, S3, o);
    }
    if ((t & 31) == 0) { r1[t >> 5] = S1; r2[t >> 5] = S2; r3[t >> 5] = S3; }
    __syncthreads();
    if (t == 0) {
        double a1 = 0, a2 = 0, a3 = 0;
        for (int w = 0; w < 8; w++) { a1 += r1[w]; a2 += r2[w]; a3 += r3[w]; }
        atomicAdd(&d_acc[0], a1);
        atomicAdd(&d_acc[1], a2);
        atomicAdd(&d_acc[2], a3);
    }
}

__global__ void finalize_kernel(float* out) {
    double S1 = d_acc[0], S2 = d_acc[1], S3 = d_acc[2];
    double v = S1 + (double)REGC * (S2 - (double)SUM_LAB * S3 - S3 + 1.0);
    out[0] = (float)v;
}

// ---------------------------------------------------------------------------
extern "C" void kernel_launch(void* const* d_in, const int* in_sizes, int n_in,
                              void* d_out, int out_size) {
    const float* X = (const float*)d_in[0];   // source [4096,512]
    const float* Y = (const float*)d_in[1];   // target [4096,512]

    init_kernel<<<16, 256>>>();
    norms_kernel<<<2 * NN, 128>>>(X, Y);
    dim3 gg(NN / BN, NN / BM);
    gemm_kernel<<<gg, 256>>>(X, Y);
    qmax_kernel<<<16, 256>>>();

    // Pair 1: f via shift (row maxes seeded exactly: g == 0), g via safe online
    f_shift_kernel<<<512, 512>>>();
    g_safe_kernel<<<128, 1024>>>();
    // Pairs 2..12: both shifted
    for (int it = 0; it < 11; it++) {
        f_shift_kernel<<<512, 512>>>();
        g_shift_kernel<<<128, 1024>>>();
    }

    // Sparse phase: 88 pairs in 3 segments with list rebuilds
    zero_cnt_kernel<<<16, 256>>>();
    build_kernel<<<256, 256>>>();
    sparse_kernel<<<8, 512>>>(30);

    zero_cnt_kernel<<<16, 256>>>();
    build_kernel<<<256, 256>>>();
    sparse_kernel<<<8, 512>>>(30);

    zero_cnt_kernel<<<16, 256>>>();
    build_kernel<<<256, 256>>>();
    sparse_kernel<<<8, 512>>>(28);

    final_kernel<<<1024, 256>>>();
    finalize_kernel<<<1, 1>>>((float*)d_out);
}

// round 14
// speedup vs baseline: 2.4481x; 1.1301x over previous
#include <cuda_runtime.h>
#include <cstdint>
#include <cstddef>
#include <math.h>

// Problem constants
#define NN 4096
#define DD 512
#define REGC 1.0f
#define INV_REG_LN2 1.4426950408889634f   // 1/(REG*ln2)
#define REG_LN2     0.6931471805599453f   // REG*ln2
#define LOG_A       (-8.317766166719343f) // -log(4096)
#define SUM_LAB     (-16.635532333438686f) // log_a + log_b
#define SHIFT_MARGIN 8.0f
#define QS      32.0f
#define INV_QS  0.03125f
#define KQ      0.045084220027780106f     // INV_REG_LN2 / 32
#define TH      34.0f                     // active-set threshold (base-2 units)
#define SCAP    96                        // entries cap per row/col

// Scratch (device globals; no allocations allowed)
__device__ unsigned short d_Mq[(size_t)NN * NN];  // 32MB quantized cost matrix
__device__ float d_f[NN], d_fs[NN];
__device__ float d_g[NN], d_gs[NN];
__device__ float d_x2[NN], d_y2[NN];
__device__ float d_rowmax[NN], d_colmax[NN];
__device__ unsigned int d_rowqmin[NN];
__device__ unsigned int d_rowcnt[NN], d_colcnt[NN];
__device__ unsigned int d_rowlist[(size_t)NN * SCAP];
__device__ unsigned int d_collist[(size_t)NN * SCAP];
__device__ double d_acc[3];

__device__ __forceinline__ float ex2f_(float x) {
    float y; asm("ex2.approx.ftz.f32 %0, %1;" : "=f"(y) : "f"(x)); return y;
}
__device__ __forceinline__ float lg2f_(float x) {
    float y; asm("lg2.approx.f32 %0, %1;" : "=f"(y) : "f"(x)); return y;
}
__device__ __forceinline__ float neg_inf_() { return __int_as_float(0xff800000); }

#define FMA2(d, a, b, c) \
    asm("fma.rn.f32x2 %0, %1, %2, %3;" : "=l"(d) : "l"(a), "l"(b), "l"(c))
#define DUP_F32X2(r, f) \
    asm("mov.b64 %0, {%1, %1};" : "=l"(r) : "r"(f))
#define UNPACK2(lo, hi, v) \
    asm("mov.b64 {%0, %1}, %2;" : "=r"(lo), "=r"(hi) : "l"(v))

__device__ __forceinline__ void lse_accum(float x, float& m, float& s) {
    float d = x - m;
    float e = ex2f_(0.f - fabsf(d));
    bool gt = d > 0.f;
    s = fmaf(s, gt ? e : 1.f, gt ? 1.f : e);
    m = gt ? x : m;
}
__device__ __forceinline__ void lse_combine(float mo, float so, float& m, float& s) {
    float mm = fmaxf(m, mo);
    s = s * ex2f_(m - mm) + so * ex2f_(mo - mm);
    m = mm;
}

// ---------------------------------------------------------------------------
__global__ void init_kernel() {
    int t = blockIdx.x * blockDim.x + threadIdx.x;
    if (t < 3) d_acc[t] = 0.0;
    if (t < NN) {
        d_g[t] = 0.f; d_gs[t] = 0.f; d_f[t] = 0.f; d_fs[t] = 0.f;
        d_rowqmin[t] = 0xffffffffu;
    }
}

__global__ void zero_cnt_kernel() {
    int t = blockIdx.x * blockDim.x + threadIdx.x;
    if (t < NN) { d_rowcnt[t] = 0u; d_colcnt[t] = 0u; }
}

// qmin -> initial row maxes (exact: g = 0 at the first f pass)
__global__ void qmax_kernel() {
    int t = blockIdx.x * blockDim.x + threadIdx.x;
    if (t < NN) d_rowmax[t] = -KQ * (float)d_rowqmin[t];
}

__global__ void norms_kernel(const float* __restrict__ X, const float* __restrict__ Y) {
    int row = blockIdx.x;
    const float* p = (row < NN) ? (X + (size_t)row * DD) : (Y + (size_t)(row - NN) * DD);
    int t = threadIdx.x;
    float4 v = ((const float4*)p)[t];
    float s = v.x * v.x + v.y * v.y + v.z * v.z + v.w * v.w;
    #pragma unroll
    for (int o = 16; o; o >>= 1) s += __shfl_down_sync(0xffffffffu, s, o);
    __shared__ float sm[4];
    if ((t & 31) == 0) sm[t >> 5] = s;
    __syncthreads();
    if (t == 0) {
        float r = sm[0] + sm[1] + sm[2] + sm[3];
        if (row < NN) d_x2[row] = r; else d_y2[row - NN] = r;
    }
}

// ---------------------------------------------------------------------------
// SGEMM: R13-proven f32x2 inner loop + DOUBLE-BUFFERED SMEM (1 sync/tile).
#define BM 128
#define BN 128
#define BK 8
__global__ void __launch_bounds__(256, 2) gemm_kernel(const float* __restrict__ X,
                                                      const float* __restrict__ Y) {
    __shared__ float As[2][BK][BM];
    __shared__ float Bs[2][BK][BN];
    __shared__ unsigned int srmin[BM];
    int tid = threadIdx.x;
    int tx = tid & 15, ty = tid >> 4;
    int bx = blockIdx.x, by = blockIdx.y;

    if (tid < BM) srmin[tid] = 0xffffu;

    int mloc = tid >> 1;
    int kq = (tid & 1) * 4;
    const float* pA = X + (size_t)(by * BM + mloc) * DD + kq;
    const float* pB = Y + (size_t)(bx * BN + mloc) * DD + kq;

    // accp[p][j] packs rows (2p, 2p+1) for column j
    unsigned long long accp[4][8];
    #pragma unroll
    for (int p = 0; p < 4; p++)
        #pragma unroll
        for (int j = 0; j < 8; j++) accp[p][j] = 0ull;

    // Prologue: tile 0 into buffer 0
    {
        float4 a4 = *(const float4*)pA;
        float4 b4 = *(const float4*)pB;
        As[0][kq + 0][mloc] = a4.x; As[0][kq + 1][mloc] = a4.y;
        As[0][kq + 2][mloc] = a4.z; As[0][kq + 3][mloc] = a4.w;
        Bs[0][kq + 0][mloc] = b4.x; Bs[0][kq + 1][mloc] = b4.y;
        Bs[0][kq + 2][mloc] = b4.z; Bs[0][kq + 3][mloc] = b4.w;
    }
    __syncthreads();

    const int NKT = DD / BK;
    for (int kt = 0; kt < NKT; kt++) {
        int cur = kt & 1;
        if (kt + 1 < NKT) {
            int nxt = cur ^ 1;
            float4 a4 = *(const float4*)(pA + (kt + 1) * BK);
            float4 b4 = *(const float4*)(pB + (kt + 1) * BK);
            As[nxt][kq + 0][mloc] = a4.x; As[nxt][kq + 1][mloc] = a4.y;
            As[nxt][kq + 2][mloc] = a4.z; As[nxt][kq + 3][mloc] = a4.w;
            Bs[nxt][kq + 0][mloc] = b4.x; Bs[nxt][kq + 1][mloc] = b4.y;
            Bs[nxt][kq + 2][mloc] = b4.z; Bs[nxt][kq + 3][mloc] = b4.w;
        }
        #pragma unroll
        for (int k = 0; k < BK; k++) {
            unsigned long long ap[4];
            #pragma unroll
            for (int p = 0; p < 4; p++)
                ap[p] = *(const unsigned long long*)(&As[cur][k][ty * 8 + 2 * p]);
            float bl[8];
            *(float4*)(&bl[0]) = *(const float4*)(&Bs[cur][k][tx * 8]);
            *(float4*)(&bl[4]) = *(const float4*)(&Bs[cur][k][tx * 8 + 4]);
            unsigned long long bd[8];
            #pragma unroll
            for (int j = 0; j < 8; j++) DUP_F32X2(bd[j], __float_as_uint(bl[j]));
            #pragma unroll
            for (int p = 0; p < 4; p++)
                #pragma unroll
                for (int j = 0; j < 8; j++)
                    FMA2(accp[p][j], ap[p], bd[j], accp[p][j]);
        }
        __syncthreads();
    }

    int r0 = by * BM + ty * 8;
    int c0 = bx * BN + tx * 8;
    float y2v[8];
    #pragma unroll
    for (int j = 0; j < 8; j++) y2v[j] = d_y2[c0 + j];
    #pragma unroll
    for (int p = 0; p < 4; p++) {
        float x2lo = d_x2[r0 + 2 * p];
        float x2hi = d_x2[r0 + 2 * p + 1];
        unsigned short qlo[8], qhi[8];
        unsigned int rminlo = 0xffffu, rminhi = 0xffffu;
        #pragma unroll
        for (int j = 0; j < 8; j++) {
            unsigned int ulo, uhi;
            UNPACK2(ulo, uhi, accp[p][j]);
            float mlo = fmaxf(x2lo + y2v[j] - 2.f * __uint_as_float(ulo), 0.f);
            float mhi = fmaxf(x2hi + y2v[j] - 2.f * __uint_as_float(uhi), 0.f);
            unsigned int q0 = __float2uint_rn(fminf(mlo * QS, 65535.f));
            unsigned int q1 = __float2uint_rn(fminf(mhi * QS, 65535.f));
            qlo[j] = (unsigned short)q0;
            qhi[j] = (unsigned short)q1;
            rminlo = min(rminlo, q0); rminhi = min(rminhi, q1);
        }
        atomicMin(&srmin[ty * 8 + 2 * p], rminlo);
        atomicMin(&srmin[ty * 8 + 2 * p + 1], rminhi);
        unsigned short* dst = d_Mq + (size_t)(r0 + 2 * p) * NN + c0;
        *(uint4*)dst = *(uint4*)qlo;
        *(uint4*)(dst + NN) = *(uint4*)qhi;
    }
    __syncthreads();
    if (tid < BM) atomicMin(&d_rowqmin[by * BM + tid], srmin[tid]);
}

// ---------------------------------------------------------------------------
// SAFE (online) g update, records col max. grid 128 x 1024. Used once.
__global__ void __launch_bounds__(1024) g_safe_kernel() {
    __shared__ float fs[NN];
    __shared__ float pm[32][33], ps[32][33];
    int t = threadIdx.x;
    for (int j = t; j < NN; j += 1024) fs[j] = d_fs[j];
    __syncthreads();
    int lane = t & 31;
    int rg = t >> 5;
    int col = blockIdx.x * 32 + lane;
    const unsigned short* Mc = d_Mq + col;
    float m0 = neg_inf_(), m1 = neg_inf_(), m2 = neg_inf_(), m3 = neg_inf_();
    float s0 = 0.f, s1 = 0.f, s2 = 0.f, s3 = 0.f;
    for (int base = 0; base < NN; base += 128) {
        int i0 = base + rg;
        float x0 = fmaf((float)Mc[(size_t)(i0      ) * NN], -KQ, fs[i0      ]);
        float x1 = fmaf((float)Mc[(size_t)(i0 + 32 ) * NN], -KQ, fs[i0 + 32 ]);
        float x2 = fmaf((float)Mc[(size_t)(i0 + 64 ) * NN], -KQ, fs[i0 + 64 ]);
        float x3 = fmaf((float)Mc[(size_t)(i0 + 96 ) * NN], -KQ, fs[i0 + 96 ]);
        lse_accum(x0, m0, s0);
        lse_accum(x1, m1, s1);
        lse_accum(x2, m2, s2);
        lse_accum(x3, m3, s3);
    }
    lse_combine(m1, s1, m0, s0);
    lse_combine(m3, s3, m2, s2);
    lse_combine(m2, s2, m0, s0);
    pm[rg][lane] = m0; ps[rg][lane] = s0;
    __syncthreads();
    int w = t >> 5;
    float m2_ = pm[lane][w];
    float s2_ = ps[lane][w];
    #pragma unroll
    for (int o = 16; o; o >>= 1) {
        float mo = __shfl_down_sync(0xffffffffu, m2_, o);
        float so = __shfl_down_sync(0xffffffffu, s2_, o);
        float mm = fmaxf(m2_, mo);
        s2_ = s2_ * ex2f_(m2_ - mm) + so * ex2f_(mo - mm);
        m2_ = mm;
    }
    if (lane == 0) {
        float lse2 = m2_ + lg2f_(s2_);
        float gv = REGC * LOG_A - REG_LN2 * lse2;
        int c = blockIdx.x * 32 + w;
        d_g[c] = gv;
        d_gs[c] = gv * INV_REG_LN2;
        d_colmax[c] = m2_;
    }
}

// ---------------------------------------------------------------------------
// SHIFTED dense f update: 512 blocks x 512 threads, 8 rows/block.
__global__ void __launch_bounds__(512) f_shift_kernel() {
    __shared__ float gs[NN];
    __shared__ float red_s[16], red_m[16];
    int t = threadIdx.x;
    for (int j = t; j < NN; j += 512) gs[j] = d_gs[j];
    __syncthreads();
    int r = t >> 6;
    int l = t & 63;
    int row = blockIdx.x * 8 + r;
    const uint4* Mr = (const uint4*)(d_Mq + (size_t)row * NN);
    const float4* G4 = (const float4*)gs;
    float C = d_rowmax[row] + SHIFT_MARGIN;
    float s0 = 0.f, s1 = 0.f, s2 = 0.f, s3 = 0.f;
    float m0 = neg_inf_(), m1 = neg_inf_(), m2 = neg_inf_(), m3 = neg_inf_();
    #pragma unroll
    for (int k = 0; k < 8; k++) {
        int idx = l + k * 64;
        uint4 v = Mr[idx];
        float4 ga = G4[2 * idx];
        float4 gb = G4[2 * idx + 1];
        float xa = fmaf((float)(v.x & 0xffffu), -KQ, ga.x);
        float xb = fmaf((float)(v.x >> 16),    -KQ, ga.y);
        float xc = fmaf((float)(v.y & 0xffffu), -KQ, ga.z);
        float xd = fmaf((float)(v.y >> 16),    -KQ, ga.w);
        float xe = fmaf((float)(v.z & 0xffffu), -KQ, gb.x);
        float xf = fmaf((float)(v.z >> 16),    -KQ, gb.y);
        float xg = fmaf((float)(v.w & 0xffffu), -KQ, gb.z);
        float xh = fmaf((float)(v.w >> 16),    -KQ, gb.w);
        s0 += ex2f_(xa - C); m0 = fmaxf(m0, xa);
        s1 += ex2f_(xb - C); m1 = fmaxf(m1, xb);
        s2 += ex2f_(xc - C); m2 = fmaxf(m2, xc);
        s3 += ex2f_(xd - C); m3 = fmaxf(m3, xd);
        s0 += ex2f_(xe - C); m0 = fmaxf(m0, xe);
        s1 += ex2f_(xf - C); m1 = fmaxf(m1, xf);
        s2 += ex2f_(xg - C); m2 = fmaxf(m2, xg);
        s3 += ex2f_(xh - C); m3 = fmaxf(m3, xh);
    }
    float s = (s0 + s1) + (s2 + s3);
    float m = fmaxf(fmaxf(m0, m1), fmaxf(m2, m3));
    #pragma unroll
    for (int o = 16; o; o >>= 1) {
        s += __shfl_down_sync(0xffffffffu, s, o);
        m = fmaxf(m, __shfl_down_sync(0xffffffffu, m, o));
    }
    if ((t & 31) == 0) { red_s[t >> 5] = s; red_m[t >> 5] = m; }
    __syncthreads();
    if (t < 8) {
        float stot = red_s[2 * t] + red_s[2 * t + 1];
        float mtot = fmaxf(red_m[2 * t], red_m[2 * t + 1]);
        int rr = blockIdx.x * 8 + t;
        float Cr = d_rowmax[rr] + SHIFT_MARGIN;
        float lse2 = Cr + lg2f_(stot);
        float fv = REGC * LOG_A - REG_LN2 * lse2;
        d_f[rr] = fv;
        d_fs[rr] = fv * INV_REG_LN2;
        d_rowmax[rr] = mtot;
    }
}

// SHIFTED dense g update.
__global__ void __launch_bounds__(1024) g_shift_kernel() {
    __shared__ float fs[NN];
    __shared__ float pm[32][33], ps[32][33];
    int t = threadIdx.x;
    for (int j = t; j < NN; j += 1024) fs[j] = d_fs[j];
    __syncthreads();
    int lane = t & 31;
    int rg = t >> 5;
    int col = blockIdx.x * 32 + lane;
    const unsigned short* Mc = d_Mq + col;
    float C = d_colmax[col] + SHIFT_MARGIN;
    float s0 = 0.f, s1 = 0.f, s2 = 0.f, s3 = 0.f;
    float m0 = neg_inf_(), m1 = neg_inf_(), m2 = neg_inf_(), m3 = neg_inf_();
    for (int base = 0; base < NN; base += 256) {
        int i0 = base + rg;
        unsigned short a0 = Mc[(size_t)(i0       ) * NN];
        unsigned short a1 = Mc[(size_t)(i0 + 32  ) * NN];
        unsigned short a2 = Mc[(size_t)(i0 + 64  ) * NN];
        unsigned short a3 = Mc[(size_t)(i0 + 96  ) * NN];
        unsigned short a4 = Mc[(size_t)(i0 + 128 ) * NN];
        unsigned short a5 = Mc[(size_t)(i0 + 160 ) * NN];
        unsigned short a6 = Mc[(size_t)(i0 + 192 ) * NN];
        unsigned short a7 = Mc[(size_t)(i0 + 224 ) * NN];
        float x0 = fmaf((float)a0, -KQ, fs[i0      ]);
        float x1 = fmaf((float)a1, -KQ, fs[i0 + 32 ]);
        float x2 = fmaf((float)a2, -KQ, fs[i0 + 64 ]);
        float x3 = fmaf((float)a3, -KQ, fs[i0 + 96 ]);
        float x4 = fmaf((float)a4, -KQ, fs[i0 + 128]);
        float x5 = fmaf((float)a5, -KQ, fs[i0 + 160]);
        float x6 = fmaf((float)a6, -KQ, fs[i0 + 192]);
        float x7 = fmaf((float)a7, -KQ, fs[i0 + 224]);
        s0 += ex2f_(x0 - C); m0 = fmaxf(m0, x0);
        s1 += ex2f_(x1 - C); m1 = fmaxf(m1, x1);
        s2 += ex2f_(x2 - C); m2 = fmaxf(m2, x2);
        s3 += ex2f_(x3 - C); m3 = fmaxf(m3, x3);
        s0 += ex2f_(x4 - C); m0 = fmaxf(m0, x4);
        s1 += ex2f_(x5 - C); m1 = fmaxf(m1, x5);
        s2 += ex2f_(x6 - C); m2 = fmaxf(m2, x6);
        s3 += ex2f_(x7 - C); m3 = fmaxf(m3, x7);
    }
    ps[rg][lane] = (s0 + s1) + (s2 + s3);
    pm[rg][lane] = fmaxf(fmaxf(m0, m1), fmaxf(m2, m3));
    __syncthreads();
    int w = t >> 5;
    float s2_ = ps[lane][w];
    float m2_ = pm[lane][w];
    #pragma unroll
    for (int o = 16; o; o >>= 1) {
        s2_ += __shfl_down_sync(0xffffffffu, s2_, o);
        m2_ = fmaxf(m2_, __shfl_down_sync(0xffffffffu, m2_, o));
    }
    if (lane == 0) {
        int c = blockIdx.x * 32 + w;
        float Cc = d_colmax[c] + SHIFT_MARGIN;
        float lse2 = Cc + lg2f_(s2_);
        float gv = REGC * LOG_A - REG_LN2 * lse2;
        d_g[c] = gv;
        d_gs[c] = gv * INV_REG_LN2;
        d_colmax[c] = m2_;
    }
}

// ---------------------------------------------------------------------------
// BUILD: scan Mq once; collect active entries per row and per column.
__global__ void __launch_bounds__(256) build_kernel() {
    __shared__ float gsm[NN];
    __shared__ float cth[NN];
    int t = threadIdx.x;
    for (int k = t; k < NN; k += 256) {
        gsm[k] = d_gs[k];
        cth[k] = d_colmax[k] - TH;
    }
    __syncthreads();
    int row0 = blockIdx.x * 16;
    for (int r = 0; r < 16; r++) {
        int row = row0 + r;
        float rth = d_rowmax[row] - TH;
        float fsv = d_fs[row];
        const uint4* Mr = (const uint4*)(d_Mq + (size_t)row * NN);
        for (int idx = t; idx < NN / 8; idx += 256) {
            uint4 v = Mr[idx];
            int j0 = idx * 8;
            unsigned int qs[8];
            qs[0] = v.x & 0xffffu; qs[1] = v.x >> 16;
            qs[2] = v.y & 0xffffu; qs[3] = v.y >> 16;
            qs[4] = v.z & 0xffffu; qs[5] = v.z >> 16;
            qs[6] = v.w & 0xffffu; qs[7] = v.w >> 16;
            #pragma unroll
            for (int h = 0; h < 8; h++) {
                int j = j0 + h;
                float qf = (float)qs[h];
                float xr = fmaf(qf, -KQ, gsm[j]);
                if (xr >= rth) {
                    unsigned int p = atomicAdd(&d_rowcnt[row], 1u);
                    if (p < SCAP) d_rowlist[(size_t)row * SCAP + p] = ((unsigned int)j << 16) | qs[h];
                }
                float xc = fmaf(qf, -KQ, fsv);
                if (xc >= cth[j]) {
                    unsigned int p = atomicAdd(&d_colcnt[j], 1u);
                    if (p < SCAP) d_collist[(size_t)j * SCAP + p] = ((unsigned int)row << 16) | qs[h];
                }
            }
        }
    }
}

// ---------------------------------------------------------------------------
// SPARSE Sinkhorn: cluster of 8 CTAs x 512 threads; thread-per-row/col.
__global__ void __launch_bounds__(512) __cluster_dims__(8, 1, 1)
sparse_kernel(int npairs) {
    __shared__ float vsh[NN];
    int t = threadIdx.x;
    int id = blockIdx.x * 512 + t;

    int nr = (int)d_rowcnt[id]; if (nr > SCAP) nr = SCAP;
    int nc = (int)d_colcnt[id]; if (nc > SCAP) nc = SCAP;
    const unsigned int* rlp = d_rowlist + (size_t)id * SCAP;
    const unsigned int* clp = d_collist + (size_t)id * SCAP;

    for (int it = 0; it < npairs; it++) {
        for (int k = t; k < NN; k += 512) vsh[k] = __ldcg(&d_gs[k]);
        __syncthreads();
        {
            float m = neg_inf_(), s = 0.f;
            for (int k = 0; k < nr; k++) {
                unsigned int e = rlp[k];
                float x = fmaf((float)(e & 0xffffu), -KQ, vsh[e >> 16]);
                lse_accum(x, m, s);
            }
            float lse2 = m + lg2f_(s);
            float fv = REGC * LOG_A - REG_LN2 * lse2;
            d_f[id] = fv;
            d_fs[id] = fv * INV_REG_LN2;
            d_rowmax[id] = m;
        }
        __threadfence();
        __syncthreads();
        asm volatile("barrier.cluster.arrive.aligned;" ::: "memory");
        asm volatile("barrier.cluster.wait.aligned;" ::: "memory");

        for (int k = t; k < NN; k += 512) vsh[k] = __ldcg(&d_fs[k]);
        __syncthreads();
        {
            float m = neg_inf_(), s = 0.f;
            for (int k = 0; k < nc; k++) {
                unsigned int e = clp[k];
                float x = fmaf((float)(e & 0xffffu), -KQ, vsh[e >> 16]);
                lse_accum(x, m, s);
            }
            float lse2 = m + lg2f_(s);
            float gv = REGC * LOG_A - REG_LN2 * lse2;   // log_b == log_a
            d_g[id] = gv;
            d_gs[id] = gv * INV_REG_LN2;
            d_colmax[id] = m;
        }
        __threadfence();
        __syncthreads();
        asm volatile("barrier.cluster.arrive.aligned;" ::: "memory");
        asm volatile("barrier.cluster.wait.aligned;" ::: "memory");
    }
}

// ---------------------------------------------------------------------------
// Final reduction: S1 = sum P*M, S2 = sum P*logP, S3 = sum P (dense, exact)
__global__ void __launch_bounds__(256) final_kernel() {
    __shared__ float gsh[NN];
    __shared__ float r1[8], r2[8], r3[8];
    int t = threadIdx.x;
    for (int j = t; j < NN; j += 256) gsh[j] = d_g[j];
    __syncthreads();
    const float4* g4 = (const float4*)gsh;
    int row0 = blockIdx.x * 4;
    float S1 = 0.f, S2 = 0.f, S3 = 0.f;
    for (int r = 0; r < 4; r++) {
        float fi = d_f[row0 + r];
        const uint2* Mr = (const uint2*)(d_Mq + (size_t)(row0 + r) * NN);
        #pragma unroll
        for (int j = t; j < NN / 4; j += 256) {
            uint2 v = Mr[j];
            float4 gv = g4[j];
            float M0 = (float)(v.x & 0xffffu) * INV_QS;
            float M1 = (float)(v.x >> 16)    * INV_QS;
            float M2 = (float)(v.y & 0xffffu) * INV_QS;
            float M3 = (float)(v.y >> 16)    * INV_QS;
            float lp0 = (fi + gv.x - M0);
            float lp1 = (fi + gv.y - M1);
            float lp2 = (fi + gv.z - M2);
            float lp3 = (fi + gv.w - M3);
            float p0 = ex2f_(lp0 * INV_REG_LN2);
            float p1 = ex2f_(lp1 * INV_REG_LN2);
            float p2 = ex2f_(lp2 * INV_REG_LN2);
            float p3 = ex2f_(lp3 * INV_REG_LN2);
            S1 = fmaf(p0, M0, fmaf(p1, M1, fmaf(p2, M2, fmaf(p3, M3, S1))));
            S2 = fmaf(p0, lp0, fmaf(p1, lp1, fmaf(p2, lp2, fmaf(p3, lp3, S2))));
            S3 += (p0 + p1) + (p2 + p3);
        }
    }
    #pragma unroll
    for (int o = 16; o; o >>= 1) {
        S1 += __shfl_down_sync(0xffffffffu, S1, o);
        S2 += __shfl_down_sync(0xffffffffu, S2, o);
        S3 += __shfl_down_sync(0xffffffffu, S3, o);
    }
    if ((t & 31) == 0) { r1[t >> 5] = S1; r2[t >> 5] = S2; r3[t >> 5] = S3; }
    __syncthreads();
    if (t == 0) {
        double a1 = 0, a2 = 0, a3 = 0;
        for (int w = 0; w < 8; w++) { a1 += r1[w]; a2 += r2[w]; a3 += r3[w]; }
        atomicAdd(&d_acc[0], a1);
        atomicAdd(&d_acc[1], a2);
        atomicAdd(&d_acc[2], a3);
    }
}

__global__ void finalize_kernel(float* out) {
    double S1 = d_acc[0], S2 = d_acc[1], S3 = d_acc[2];
    double v = S1 + (double)REGC * (S2 - (double)SUM_LAB * S3 - S3 + 1.0);
    out[0] = (float)v;
}

// ---------------------------------------------------------------------------
extern "C" void kernel_launch(void* const* d_in, const int* in_sizes, int n_in,
                              void* d_out, int out_size) {
    const float* X = (const float*)d_in[0];   // source [4096,512]
    const float* Y = (const float*)d_in[1];   // target [4096,512]

    init_kernel<<<16, 256>>>();
    norms_kernel<<<2 * NN, 128>>>(X, Y);
    dim3 gg(NN / BN, NN / BM);
    gemm_kernel<<<gg, 256>>>(X, Y);
    qmax_kernel<<<16, 256>>>();

    // Pair 1: f via shift (row maxes seeded exactly: g == 0), g via safe online
    f_shift_kernel<<<512, 512>>>();
    g_safe_kernel<<<128, 1024>>>();
    // Pairs 2..12: both shifted
    for (int it = 0; it < 11; it++) {
        f_shift_kernel<<<512, 512>>>();
        g_shift_kernel<<<128, 1024>>>();
    }

    // Sparse phase: 64 pairs in 2 segments with list rebuilds
    // (iterates are quantization-converged well before pair 100; see R13 notes)
    zero_cnt_kernel<<<16, 256>>>();
    build_kernel<<<256, 256>>>();
    sparse_kernel<<<8, 512>>>(32);

    zero_cnt_kernel<<<16, 256>>>();
    build_kernel<<<256, 256>>>();
    sparse_kernel<<<8, 512>>>(32);

    final_kernel<<<1024, 256>>>();
    finalize_kernel<<<1, 1>>>((float*)d_out);
}